// round 5
// baseline (speedup 1.0000x reference)
#include <cuda_runtime.h>
#include <math_constants.h>

#define B_   512
#define N_   64
#define K_   16
#define NB_  32768      // B_*N_
#define NE_  524288     // NB_*K_
#define EPS_ 1e-5f

// ---------------- scratch (device globals; no allocation allowed) ----------------
__device__ float g_h0[NB_*64];
__device__ float g_h1[NB_*64];
__device__ float g_h2[NB_*128];
__device__ float g_h3[NB_*256];
__device__ int   g_idx[NE_];
__device__ float g_u[NB_*256];
__device__ float g_y[NB_*256];
__device__ float g_hb[(size_t)NE_*256];   // 512 MB: raw layer-b pre-activations
__device__ float g_pool[B_*896];
__device__ float g_z1[B_*512];
__device__ float g_z2[B_*256];
__device__ double g_stat[10][2][512];     // fp64: [bn id][sum,sumsq][channel]
__device__ float  g_coef[10][2][512];     // precomputed BN scale/shift per channel

__device__ __forceinline__ float* pickbuf(int s){
    switch (s){ case 0: return g_h0; case 1: return g_h1; case 2: return g_h2; default: return g_h3; }
}

__device__ __forceinline__ float lrelu(float v){ return v >= 0.f ? v : 0.2f*v; }

// ---------------- packed fp32x2 (Blackwell double-rate fp32) ----------------
typedef unsigned long long u64;
__device__ __forceinline__ u64 pk2(float lo, float hi){
    u64 r; asm("mov.b64 %0, {%1, %2};" : "=l"(r) : "f"(lo), "f"(hi)); return r;
}
__device__ __forceinline__ void fma2(u64& d, u64 a, u64 b){
    asm("fma.rn.f32x2 %0, %1, %2, %0;" : "+l"(d) : "l"(a), "l"(b));
}
__device__ __forceinline__ float2 up2(u64 v){
    float lo, hi; asm("mov.b64 {%0, %1}, %2;" : "=f"(lo), "=f"(hi) : "l"(v));
    return make_float2(lo, hi);
}

// ---------------- kernels ----------------
__global__ void k_zero(){
    int i = blockIdx.x*blockDim.x + threadIdx.x;
    if (i < 10*2*512) ((double*)g_stat)[i] = 0.0;
}

// BN coefficients from fp64 stats: y = h*sc + sh
__global__ void k_coef(int sid, float cnt, const float* __restrict__ g, const float* __restrict__ b){
    int c = threadIdx.x;
    double s1 = g_stat[sid][0][c], s2 = g_stat[sid][1][c];
    double m = s1 / (double)cnt;
    double v = s2 / (double)cnt - m*m;
    float r = rsqrtf((float)v + EPS_);
    float sc = g[c]*r;
    g_coef[sid][0][c] = sc;
    g_coef[sid][1][c] = b[c] - (float)m*sc;
}

// h0_raw = x @ w_in  (32768 x 6 -> 64), stats id 0
__global__ void k_lin_in(const float* __restrict__ x, const float* __restrict__ w){
    int c = threadIdx.x;              // 64
    int row0 = blockIdx.x*16;
    float wl[6];
    #pragma unroll
    for (int j=0;j<6;j++) wl[j] = w[j*64+c];
    double s1=0.0, s2=0.0;
    for (int r=0;r<16;r++){
        int row = row0+r;
        float a = 0.f;
        #pragma unroll
        for (int j=0;j<6;j++) a += x[row*6+j]*wl[j];
        g_h0[row*64+c] = a;
        double ad = (double)a;
        s1 += ad; s2 += ad*ad;
    }
    atomicAdd(&g_stat[0][0][c], s1);
    atomicAdd(&g_stat[0][1][c], s2);
}

__global__ void k_bnact0(){
    int i = blockIdx.x*blockDim.x + threadIdx.x;
    if (i >= NB_*64) return;
    int c = i & 63;
    float sc = g_coef[0][0][c], sh = g_coef[0][1][c];
    g_h0[i] = lrelu(g_h0[i]*sc + sh);
}

// exact replication of jax: top_k(-d, 17) stable (ties -> lower index), drop entry 0
template<int C>
__global__ void k_knn(int src){
    __shared__ float xs[64][C+1];
    __shared__ float sq[64];
    const float* xin = pickbuf(src);
    int b = blockIdx.x, n = threadIdx.x;   // 64 threads
    const float* xb = xin + (size_t)b*64*C;
    for (int t=n; t<64*C; t+=64) xs[t/C][t%C] = xb[t];
    __syncthreads();
    float s = 0.f;
    #pragma unroll 8
    for (int c2=0;c2<C;c2++) s += xs[n][c2]*xs[n][c2];
    sq[n] = s;
    __syncthreads();
    float dl[64];
    for (int m=0;m<64;m++){
        float dot = 0.f;
        #pragma unroll 8
        for (int c2=0;c2<C;c2++) dot += xs[n][c2]*xs[m][c2];
        dl[m] = sq[n] - 2.f*dot + sq[m];
    }
    float pd = -CUDART_INF_F; int pi = -1;
    int out_base = (b*64+n)*K_;
    for (int t=0;t<17;t++){
        float bd = CUDART_INF_F; int bi = 1<<30;
        #pragma unroll
        for (int m=0;m<64;m++){
            float d = dl[m];
            bool gtp = (d > pd) || (d == pd && m > pi);
            bool ltb = (d < bd) || (d == bd && m < bi);
            if (gtp && ltb){ bd = d; bi = m; }
        }
        if (t > 0) g_idx[out_base + (t-1)] = bi;
        pd = bd; pi = bi;
    }
}

// u = x @ W_bot ; y = x @ (W_top - W_bot)   (32768 rows, layer-a factorization)
template<int CI, int CO>
__global__ void k_gemm_uy(int src, const float* __restrict__ W){
    __shared__ float xs[8][CI];
    const float* xin = pickbuf(src);
    int c = threadIdx.x;              // CO threads
    int row0 = blockIdx.x*8;
    for (int t=c; t<8*CI; t+=CO) xs[t/CI][t%CI] = xin[(size_t)row0*CI + t];
    __syncthreads();
    float ua[8] = {0,0,0,0,0,0,0,0};
    float ya[8] = {0,0,0,0,0,0,0,0};
    for (int j=0;j<CI;j++){
        float wt = W[j*CO + c];
        float wb = W[(CI+j)*CO + c];
        float wd = wt - wb;
        #pragma unroll
        for (int r=0;r<8;r++){ float xv = xs[r][j]; ua[r] += xv*wb; ya[r] += xv*wd; }
    }
    #pragma unroll
    for (int r=0;r<8;r++){
        g_u[(size_t)(row0+r)*CO + c] = ua[r];
        g_y[(size_t)(row0+r)*CO + c] = ya[r];
    }
}

// layer-a stats over all edges: v = u[center] + y[neighbor]  (fp64 accumulate)
template<int CO>
__global__ void k_stats_a(int sid){
    int b = blockIdx.x, c = threadIdx.x;   // CO threads
    double s1=0.0, s2=0.0;
    for (int n=0;n<64;n++){
        int row = b*64+n;
        float uv = g_u[(size_t)row*CO + c];
        #pragma unroll
        for (int k=0;k<K_;k++){
            int j = g_idx[row*K_ + k];
            float v = uv + g_y[(size_t)(b*64+j)*CO + c];
            double vd = (double)v;
            s1 += vd; s2 += vd*vd;
        }
    }
    atomicAdd(&g_stat[sid][0][c], s1);
    atomicAdd(&g_stat[sid][1][c], s2);
}

// layer-b: hb = lrelu(bn_a(u+y)) @ Wb, raw hb materialized + stats_b (fp64).
// fp32x2 inner loop: pair of j per LDS.64, 2 output channels per thread.
template<int CI, int CO>
__global__ void k_gemm_b(const float* __restrict__ W, int sid_a, int sid_b){
    const int H = CO/2;                       // threads per block
    __shared__ __align__(8) float act[K_][CI];
    __shared__ float us[CI];
    __shared__ int id[K_];
    int tid = threadIdx.x;
    int row = blockIdx.x;                      // (b,n)
    int base = row & ~63;                      // b*64
    for (int j=tid; j<CI; j+=H) us[j] = g_u[(size_t)row*CI + j];
    if (tid < K_) id[tid] = g_idx[row*K_ + tid];
    __syncthreads();
    for (int t=tid; t<K_*CI; t+=H){
        int k = t/CI, j = t - k*CI;
        float v = us[j] + g_y[(size_t)(base+id[k])*CI + j];
        act[k][j] = lrelu(v*g_coef[sid_a][0][j] + g_coef[sid_a][1][j]);
    }
    __syncthreads();

    u64 accA[K_], accB[K_];
    #pragma unroll
    for (int k=0;k<K_;k++){ accA[k]=0ull; accB[k]=0ull; }
    int cA = tid, cB = tid + H;
    for (int jj=0; jj<CI/2; jj++){
        int j0 = jj*2;
        u64 wA = pk2(W[j0*CO + cA], W[(j0+1)*CO + cA]);
        u64 wB = pk2(W[j0*CO + cB], W[(j0+1)*CO + cB]);
        #pragma unroll
        for (int k=0;k<K_;k++){
            u64 f = *(const u64*)&act[k][j0];
            fma2(accA[k], f, wA);
            fma2(accB[k], f, wB);
        }
    }
    double s1A=0.0,s2A=0.0,s1B=0.0,s2B=0.0;
    #pragma unroll
    for (int k=0;k<K_;k++){
        float2 a = up2(accA[k]); float vA = a.x + a.y;
        float2 q = up2(accB[k]); float vB = q.x + q.y;
        g_hb[(size_t)(row*K_+k)*CO + cA] = vA;
        g_hb[(size_t)(row*K_+k)*CO + cB] = vB;
        double dA=(double)vA, dB=(double)vB;
        s1A+=dA; s2A+=dA*dA; s1B+=dB; s2B+=dB*dB;
    }
    atomicAdd(&g_stat[sid_b][0][cA], s1A);
    atomicAdd(&g_stat[sid_b][1][cA], s2A);
    atomicAdd(&g_stat[sid_b][0][cB], s1B);
    atomicAdd(&g_stat[sid_b][1][cB], s2B);
}

// scatter-max of lrelu(bn_b(hb)) into destination nodes (by neighbor index), -inf -> 0
template<int CO>
__global__ void k_scatter(int sid, int dst){
    __shared__ int   id[1024];
    __shared__ int   cnt[64];
    __shared__ int   off[65];
    __shared__ short lst[1024];
    float* out = pickbuf(dst);
    int b = blockIdx.x, c = threadIdx.x;   // CO threads
    float sc = g_coef[sid][0][c], sh = g_coef[sid][1][c];
    if (c < 64) cnt[c] = 0;
    __syncthreads();
    for (int t=c; t<1024; t+=CO){ int v = g_idx[b*1024+t]; id[t]=v; atomicAdd(&cnt[v],1); }
    __syncthreads();
    if (c == 0){ int acc=0; for (int i=0;i<64;i++){ off[i]=acc; acc+=cnt[i]; } off[64]=acc; }
    __syncthreads();
    if (c < 64) cnt[c] = 0;
    __syncthreads();
    for (int t=c; t<1024; t+=CO){ int v=id[t]; int p = off[v] + atomicAdd(&cnt[v],1); lst[p]=(short)t; }
    __syncthreads();
    const float* hbb = g_hb + (size_t)b*1024*CO;
    for (int i=0;i<64;i++){
        float m = -CUDART_INF_F;
        int e0 = off[i], e1 = off[i+1];
        for (int e=e0; e<e1; e++){
            int t = lst[e];
            float v = hbb[(size_t)t*CO + c];
            v = lrelu(v*sc + sh);
            m = fmaxf(m, v);
        }
        out[(size_t)(b*64+i)*CO + c] = (e1 > e0) ? m : 0.f;
    }
}

// pooled = [mean_n h1|h2|h3 , max_n h1|h2|h3]  -> (512, 896)
__global__ void k_pool(){
    int b = blockIdx.x, c = threadIdx.x;   // 448
    const float* src; int ch, C;
    if (c < 64)       { src = g_h1; ch = c;      C = 64;  }
    else if (c < 192) { src = g_h2; ch = c-64;   C = 128; }
    else              { src = g_h3; ch = c-192;  C = 256; }
    float s = 0.f, m = -CUDART_INF_F;
    for (int n=0;n<64;n++){
        float v = src[(size_t)(b*64+n)*C + ch];
        s += v; m = fmaxf(m, v);
    }
    g_pool[b*896 + c]       = s * (1.f/64.f);
    g_pool[b*896 + 448 + c] = m;
}

__global__ void k_fc1(const float* __restrict__ W){
    __shared__ float p[896];
    int b = blockIdx.x, c = threadIdx.x;   // 512
    for (int t=c; t<896; t+=512) p[t] = g_pool[b*896+t];
    __syncthreads();
    float a = 0.f;
    for (int j=0;j<896;j++) a += p[j]*W[j*512+c];
    g_z1[b*512+c] = a;
    double ad = (double)a;
    atomicAdd(&g_stat[7][0][c], ad);
    atomicAdd(&g_stat[7][1][c], ad*ad);
}

__global__ void k_fc2(const float* __restrict__ W){
    __shared__ float p[512];
    int b = blockIdx.x, c = threadIdx.x;   // 256
    for (int t=c; t<512; t+=256){
        p[t] = lrelu(g_z1[b*512+t]*g_coef[7][0][t] + g_coef[7][1][t]);
    }
    __syncthreads();
    float a = 0.f;
    for (int j=0;j<512;j++) a += p[j]*W[j*256+c];
    g_z2[b*256+c] = a;
    double ad = (double)a;
    atomicAdd(&g_stat[8][0][c], ad);
    atomicAdd(&g_stat[8][1][c], ad*ad);
}

__global__ void k_out(const float* __restrict__ W, const float* __restrict__ bc,
                      float* __restrict__ out){
    __shared__ float r0[256], r1[256];
    int b = blockIdx.x, j = threadIdx.x;   // 256
    float v = lrelu(g_z2[b*256+j]*g_coef[8][0][j] + g_coef[8][1][j]);
    r0[j] = v*W[j*2+0];
    r1[j] = v*W[j*2+1];
    __syncthreads();
    for (int s=128; s>0; s>>=1){
        if (j < s){ r0[j]+=r0[j+s]; r1[j]+=r1[j+s]; }
        __syncthreads();
    }
    if (j==0){ out[b*2+0] = r0[0]+bc[0]; out[b*2+1] = r1[0]+bc[1]; }
}

// ---------------- launch ----------------
extern "C" void kernel_launch(void* const* d_in, const int* in_sizes, int n_in,
                              void* d_out, int out_size){
    const float* x    = (const float*)d_in[0];
    // d_in[1] = batch (unused by reference body)
    const float* w_in = (const float*)d_in[2];
    const float* gin  = (const float*)d_in[3];
    const float* bin  = (const float*)d_in[4];
    const float* w1a  = (const float*)d_in[5];
    const float* g1a  = (const float*)d_in[6];
    const float* b1a  = (const float*)d_in[7];
    const float* w1b  = (const float*)d_in[8];
    const float* g1b  = (const float*)d_in[9];
    const float* b1b  = (const float*)d_in[10];
    const float* w2a  = (const float*)d_in[11];
    const float* g2a  = (const float*)d_in[12];
    const float* b2a  = (const float*)d_in[13];
    const float* w2b  = (const float*)d_in[14];
    const float* g2b  = (const float*)d_in[15];
    const float* b2b  = (const float*)d_in[16];
    const float* w3a  = (const float*)d_in[17];
    const float* g3a  = (const float*)d_in[18];
    const float* b3a  = (const float*)d_in[19];
    const float* w3b  = (const float*)d_in[20];
    const float* g3b  = (const float*)d_in[21];
    const float* b3b  = (const float*)d_in[22];
    const float* wc1  = (const float*)d_in[23];
    const float* gc1  = (const float*)d_in[24];
    const float* bc1  = (const float*)d_in[25];
    const float* wc2  = (const float*)d_in[26];
    const float* gc2  = (const float*)d_in[27];
    const float* bc2  = (const float*)d_in[28];
    const float* wc3  = (const float*)d_in[29];
    const float* bc3  = (const float*)d_in[30];

    k_zero<<<40, 256>>>();
    k_lin_in<<<NB_/16, 64>>>(x, w_in);
    k_coef<<<1, 64>>>(0, (float)NB_, gin, bin);
    k_bnact0<<<(NB_*64 + 255)/256, 256>>>();

    // edge conv 1: in 64 ch -> 64
    k_knn<64><<<B_, 64>>>(0);
    k_gemm_uy<64,64><<<NB_/8, 64>>>(0, w1a);
    k_stats_a<64><<<B_, 64>>>(1);
    k_coef<<<1, 64>>>(1, (float)NE_, g1a, b1a);
    k_gemm_b<64,64><<<NB_, 32>>>(w1b, 1, 2);
    k_coef<<<1, 64>>>(2, (float)NE_, g1b, b1b);
    k_scatter<64><<<B_, 64>>>(2, 1);

    // edge conv 2: in 64 ch -> 128
    k_knn<64><<<B_, 64>>>(1);
    k_gemm_uy<64,128><<<NB_/8, 128>>>(1, w2a);
    k_stats_a<128><<<B_, 128>>>(3);
    k_coef<<<1, 128>>>(3, (float)NE_, g2a, b2a);
    k_gemm_b<128,128><<<NB_, 64>>>(w2b, 3, 4);
    k_coef<<<1, 128>>>(4, (float)NE_, g2b, b2b);
    k_scatter<128><<<B_, 128>>>(4, 2);

    // edge conv 3: in 128 ch -> 256
    k_knn<128><<<B_, 64>>>(2);
    k_gemm_uy<128,256><<<NB_/8, 256>>>(2, w3a);
    k_stats_a<256><<<B_, 256>>>(5);
    k_coef<<<1, 256>>>(5, (float)NE_, g3a, b3a);
    k_gemm_b<256,256><<<NB_, 128>>>(w3b, 5, 6);
    k_coef<<<1, 256>>>(6, (float)NE_, g3b, b3b);
    k_scatter<256><<<B_, 256>>>(6, 3);

    // head
    k_pool<<<B_, 448>>>();
    k_fc1<<<B_, 512>>>(wc1);
    k_coef<<<1, 512>>>(7, (float)B_, gc1, bc1);
    k_fc2<<<B_, 256>>>(wc2);
    k_coef<<<1, 256>>>(8, (float)B_, gc2, bc2);
    k_out<<<B_, 256>>>(wc3, bc3, (float*)d_out);
}

// round 7
// speedup vs baseline: 1.4085x; 1.4085x over previous
#include <cuda_runtime.h>
#include <math_constants.h>

#define B_   512
#define N_   64
#define K_   16
#define NB_  32768      // B_*N_
#define NE_  524288     // NB_*K_
#define EPS_ 1e-5f

// ---------------- scratch (device globals; no allocation allowed) ----------------
__device__ float g_h0[NB_*64];
__device__ float g_h1[NB_*64];
__device__ float g_h2[NB_*128];
__device__ float g_h3[NB_*256];
__device__ int   g_idx[NE_];
__device__ float g_u[NB_*256];
__device__ float g_y[NB_*256];
__device__ float g_hb[(size_t)NE_*256];   // 512 MB: raw layer-b pre-activations
__device__ float g_pool[B_*896];
__device__ float g_z1[B_*512];
__device__ float g_z2[B_*256];
__device__ double g_stat[10][2][512];     // fp64: [bn id][sum,sumsq][channel]
__device__ float  g_coef[10][2][512];     // precomputed BN scale/shift per channel

__device__ __forceinline__ float* pickbuf(int s){
    switch (s){ case 0: return g_h0; case 1: return g_h1; case 2: return g_h2; default: return g_h3; }
}

__device__ __forceinline__ float lrelu(float v){ return v >= 0.f ? v : 0.2f*v; }

// ---------------- packed fp32x2 (Blackwell double-rate fp32) ----------------
typedef unsigned long long u64;
__device__ __forceinline__ u64 pk2(float lo, float hi){
    u64 r; asm("mov.b64 %0, {%1, %2};" : "=l"(r) : "f"(lo), "f"(hi)); return r;
}
__device__ __forceinline__ void fma2(u64& d, u64 a, u64 b){
    asm("fma.rn.f32x2 %0, %1, %2, %0;" : "+l"(d) : "l"(a), "l"(b));
}
__device__ __forceinline__ float2 up2(u64 v){
    float lo, hi; asm("mov.b64 {%0, %1}, %2;" : "=f"(lo), "=f"(hi) : "l"(v));
    return make_float2(lo, hi);
}

// ---------------- kernels ----------------
__global__ void k_zero(){
    int i = blockIdx.x*blockDim.x + threadIdx.x;
    if (i < 10*2*512) ((double*)g_stat)[i] = 0.0;
}

// BN coefficients from fp64 stats: y = h*sc + sh
__global__ void k_coef(int sid, float cnt, const float* __restrict__ g, const float* __restrict__ b){
    int c = threadIdx.x;
    double s1 = g_stat[sid][0][c], s2 = g_stat[sid][1][c];
    double m = s1 / (double)cnt;
    double v = s2 / (double)cnt - m*m;
    float r = rsqrtf((float)v + EPS_);
    float sc = g[c]*r;
    g_coef[sid][0][c] = sc;
    g_coef[sid][1][c] = b[c] - (float)m*sc;
}

// h0_raw = x @ w_in  (32768 x 6 -> 64), stats id 0
__global__ void k_lin_in(const float* __restrict__ x, const float* __restrict__ w){
    int c = threadIdx.x;              // 64
    int row0 = blockIdx.x*16;
    float wl[6];
    #pragma unroll
    for (int j=0;j<6;j++) wl[j] = w[j*64+c];
    float s1=0.f, s2=0.f;            // 16-term fp32 inner, fp64 only at atomic
    for (int r=0;r<16;r++){
        int row = row0+r;
        float a = 0.f;
        #pragma unroll
        for (int j=0;j<6;j++) a += x[row*6+j]*wl[j];
        g_h0[row*64+c] = a;
        s1 += a; s2 += a*a;
    }
    atomicAdd(&g_stat[0][0][c], (double)s1);
    atomicAdd(&g_stat[0][1][c], (double)s2);
}

__global__ void k_bnact0(){
    int i = blockIdx.x*blockDim.x + threadIdx.x;
    if (i >= NB_*64) return;
    int c = i & 63;
    float sc = g_coef[0][0][c], sh = g_coef[0][1][c];
    g_h0[i] = lrelu(g_h0[i]*sc + sh);
}

// exact replication of jax: top_k(-d, 17) stable (ties -> lower index), drop entry 0
// fp32x2 packed distance computation.
template<int C>
__global__ void k_knn(int src){
    const int C2 = C/2;
    __shared__ __align__(8) float2 xs[64][C/2 + 1];
    __shared__ float sq[64];
    const float* xin = pickbuf(src);
    int b = blockIdx.x, n = threadIdx.x;   // 64 threads
    const float2* xb = (const float2*)(xin + (size_t)b*64*C);
    for (int t=n; t<64*C2; t+=64){ int r=t/C2, c2=t-r*C2; xs[r][c2] = xb[t]; }
    __syncthreads();
    {
        u64 acc = 0ull;
        #pragma unroll 8
        for (int c2=0;c2<C2;c2++){ u64 v = *(const u64*)&xs[n][c2]; fma2(acc, v, v); }
        float2 a = up2(acc);
        sq[n] = a.x + a.y;
    }
    __syncthreads();
    float dl[64];
    for (int m=0;m<64;m++){
        u64 acc = 0ull;
        #pragma unroll 8
        for (int c2=0;c2<C2;c2++)
            fma2(acc, *(const u64*)&xs[n][c2], *(const u64*)&xs[m][c2]);
        float2 d2 = up2(acc);
        dl[m] = sq[n] - 2.f*(d2.x + d2.y) + sq[m];
    }
    float pd = -CUDART_INF_F; int pi = -1;
    int out_base = (b*64+n)*K_;
    for (int t=0;t<17;t++){
        float bd = CUDART_INF_F; int bi = 1<<30;
        #pragma unroll
        for (int m=0;m<64;m++){
            float d = dl[m];
            bool gtp = (d > pd) || (d == pd && m > pi);
            bool ltb = (d < bd) || (d == bd && m < bi);
            if (gtp && ltb){ bd = d; bi = m; }
        }
        if (t > 0) g_idx[out_base + (t-1)] = bi;
        pd = bd; pi = bi;
    }
}

// u = x @ W_bot ; y = x @ (W_top - W_bot)   (layer-a factorization, fp32x2)
template<int CI, int CO>
__global__ void k_gemm_uy(int src, const float* __restrict__ W){
    __shared__ __align__(8) float xs[8][CI];
    const float* xin = pickbuf(src);
    int c = threadIdx.x;              // CO threads
    int row0 = blockIdx.x*8;
    for (int t=c; t<8*CI; t+=CO) xs[t/CI][t%CI] = xin[(size_t)row0*CI + t];
    __syncthreads();
    u64 ua[8], ya[8];
    #pragma unroll
    for (int r=0;r<8;r++){ ua[r]=0ull; ya[r]=0ull; }
    for (int j2=0;j2<CI/2;j2++){
        int j0 = 2*j2;
        float wt0 = W[j0*CO + c],      wt1 = W[(j0+1)*CO + c];
        float wb0 = W[(CI+j0)*CO + c], wb1 = W[(CI+j0+1)*CO + c];
        u64 wb = pk2(wb0, wb1);
        u64 wd = pk2(wt0-wb0, wt1-wb1);
        #pragma unroll
        for (int r=0;r<8;r++){
            u64 xv = *(const u64*)&xs[r][j0];
            fma2(ua[r], xv, wb);
            fma2(ya[r], xv, wd);
        }
    }
    #pragma unroll
    for (int r=0;r<8;r++){
        float2 a = up2(ua[r]);
        float2 q = up2(ya[r]);
        g_u[(size_t)(row0+r)*CO + c] = a.x + a.y;
        g_y[(size_t)(row0+r)*CO + c] = q.x + q.y;
    }
}

// layer-a stats over all edges: v = u[center] + y[neighbor]
// fp32 16-term inner sums; fp64 only for the long outer accumulation.
template<int CO>
__global__ void k_stats_a(int sid){
    int b = blockIdx.x, c = threadIdx.x;   // CO threads
    double s1=0.0, s2=0.0;
    for (int n=0;n<64;n++){
        int row = b*64+n;
        float uv = g_u[(size_t)row*CO + c];
        float f1=0.f, f2=0.f;
        #pragma unroll
        for (int k=0;k<K_;k++){
            int j = g_idx[row*K_ + k];
            float v = uv + g_y[(size_t)(b*64+j)*CO + c];
            f1 += v; f2 += v*v;
        }
        s1 += (double)f1; s2 += (double)f2;
    }
    atomicAdd(&g_stat[sid][0][c], s1);
    atomicAdd(&g_stat[sid][1][c], s2);
}

// layer-b: hb = lrelu(bn_a(u+y)) @ Wb, raw hb materialized + stats_b.
// fp32x2 inner loop; stats: fp32 16-term, single fp64 atomic.
template<int CI, int CO>
__global__ void k_gemm_b(const float* __restrict__ W, int sid_a, int sid_b){
    const int H = CO/2;                       // threads per block
    __shared__ __align__(8) float act[K_][CI];
    __shared__ float us[CI];
    __shared__ int id[K_];
    int tid = threadIdx.x;
    int row = blockIdx.x;                      // (b,n)
    int base = row & ~63;                      // b*64
    for (int j=tid; j<CI; j+=H) us[j] = g_u[(size_t)row*CI + j];
    if (tid < K_) id[tid] = g_idx[row*K_ + tid];
    __syncthreads();
    for (int t=tid; t<K_*CI; t+=H){
        int k = t/CI, j = t - k*CI;
        float v = us[j] + g_y[(size_t)(base+id[k])*CI + j];
        act[k][j] = lrelu(v*g_coef[sid_a][0][j] + g_coef[sid_a][1][j]);
    }
    __syncthreads();

    u64 accA[K_], accB[K_];
    #pragma unroll
    for (int k=0;k<K_;k++){ accA[k]=0ull; accB[k]=0ull; }
    int cA = tid, cB = tid + H;
    for (int jj=0; jj<CI/2; jj++){
        int j0 = jj*2;
        u64 wA = pk2(W[j0*CO + cA], W[(j0+1)*CO + cA]);
        u64 wB = pk2(W[j0*CO + cB], W[(j0+1)*CO + cB]);
        #pragma unroll
        for (int k=0;k<K_;k++){
            u64 f = *(const u64*)&act[k][j0];
            fma2(accA[k], f, wA);
            fma2(accB[k], f, wB);
        }
    }
    float s1A=0.f,s2A=0.f,s1B=0.f,s2B=0.f;
    #pragma unroll
    for (int k=0;k<K_;k++){
        float2 a = up2(accA[k]); float vA = a.x + a.y;
        float2 q = up2(accB[k]); float vB = q.x + q.y;
        g_hb[(size_t)(row*K_+k)*CO + cA] = vA;
        g_hb[(size_t)(row*K_+k)*CO + cB] = vB;
        s1A+=vA; s2A+=vA*vA; s1B+=vB; s2B+=vB*vB;
    }
    atomicAdd(&g_stat[sid_b][0][cA], (double)s1A);
    atomicAdd(&g_stat[sid_b][1][cA], (double)s2A);
    atomicAdd(&g_stat[sid_b][0][cB], (double)s1B);
    atomicAdd(&g_stat[sid_b][1][cB], (double)s2B);
}

// scatter-max of lrelu(bn_b(hb)) into destination nodes (by neighbor index), -inf -> 0
template<int CO>
__global__ void k_scatter(int sid, int dst){
    __shared__ int   id[1024];
    __shared__ int   cnt[64];
    __shared__ int   off[65];
    __shared__ short lst[1024];
    float* out = pickbuf(dst);
    int b = blockIdx.x, c = threadIdx.x;   // CO threads
    float sc = g_coef[sid][0][c], sh = g_coef[sid][1][c];
    if (c < 64) cnt[c] = 0;
    __syncthreads();
    for (int t=c; t<1024; t+=CO){ int v = g_idx[b*1024+t]; id[t]=v; atomicAdd(&cnt[v],1); }
    __syncthreads();
    if (c == 0){ int acc=0; for (int i=0;i<64;i++){ off[i]=acc; acc+=cnt[i]; } off[64]=acc; }
    __syncthreads();
    if (c < 64) cnt[c] = 0;
    __syncthreads();
    for (int t=c; t<1024; t+=CO){ int v=id[t]; int p = off[v] + atomicAdd(&cnt[v],1); lst[p]=(short)t; }
    __syncthreads();
    const float* hbb = g_hb + (size_t)b*1024*CO;
    for (int i=0;i<64;i++){
        float m = -CUDART_INF_F;
        int e0 = off[i], e1 = off[i+1];
        for (int e=e0; e<e1; e++){
            int t = lst[e];
            float v = hbb[(size_t)t*CO + c];
            v = lrelu(v*sc + sh);
            m = fmaxf(m, v);
        }
        out[(size_t)(b*64+i)*CO + c] = (e1 > e0) ? m : 0.f;
    }
}

// pooled = [mean_n h1|h2|h3 , max_n h1|h2|h3]  -> (512, 896)
__global__ void k_pool(){
    int b = blockIdx.x, c = threadIdx.x;   // 448
    const float* src; int ch, C;
    if (c < 64)       { src = g_h1; ch = c;      C = 64;  }
    else if (c < 192) { src = g_h2; ch = c-64;   C = 128; }
    else              { src = g_h3; ch = c-192;  C = 256; }
    float s = 0.f, m = -CUDART_INF_F;
    for (int n=0;n<64;n++){
        float v = src[(size_t)(b*64+n)*C + ch];
        s += v; m = fmaxf(m, v);
    }
    g_pool[b*896 + c]       = s * (1.f/64.f);
    g_pool[b*896 + 448 + c] = m;
}

__global__ void k_fc1(const float* __restrict__ W){
    __shared__ float p[896];
    int b = blockIdx.x, c = threadIdx.x;   // 512
    for (int t=c; t<896; t+=512) p[t] = g_pool[b*896+t];
    __syncthreads();
    float a = 0.f;
    for (int j=0;j<896;j++) a += p[j]*W[j*512+c];
    g_z1[b*512+c] = a;
    double ad = (double)a;
    atomicAdd(&g_stat[7][0][c], ad);
    atomicAdd(&g_stat[7][1][c], ad*ad);
}

__global__ void k_fc2(const float* __restrict__ W){
    __shared__ float p[512];
    int b = blockIdx.x, c = threadIdx.x;   // 256
    for (int t=c; t<512; t+=256){
        p[t] = lrelu(g_z1[b*512+t]*g_coef[7][0][t] + g_coef[7][1][t]);
    }
    __syncthreads();
    float a = 0.f;
    for (int j=0;j<512;j++) a += p[j]*W[j*256+c];
    g_z2[b*256+c] = a;
    double ad = (double)a;
    atomicAdd(&g_stat[8][0][c], ad);
    atomicAdd(&g_stat[8][1][c], ad*ad);
}

__global__ void k_out(const float* __restrict__ W, const float* __restrict__ bc,
                      float* __restrict__ out){
    __shared__ float r0[256], r1[256];
    int b = blockIdx.x, j = threadIdx.x;   // 256
    float v = lrelu(g_z2[b*256+j]*g_coef[8][0][j] + g_coef[8][1][j]);
    r0[j] = v*W[j*2+0];
    r1[j] = v*W[j*2+1];
    __syncthreads();
    for (int s=128; s>0; s>>=1){
        if (j < s){ r0[j]+=r0[j+s]; r1[j]+=r1[j+s]; }
        __syncthreads();
    }
    if (j==0){ out[b*2+0] = r0[0]+bc[0]; out[b*2+1] = r1[0]+bc[1]; }
}

// ---------------- launch ----------------
extern "C" void kernel_launch(void* const* d_in, const int* in_sizes, int n_in,
                              void* d_out, int out_size){
    const float* x    = (const float*)d_in[0];
    // d_in[1] = batch (unused by reference body)
    const float* w_in = (const float*)d_in[2];
    const float* gin  = (const float*)d_in[3];
    const float* bin  = (const float*)d_in[4];
    const float* w1a  = (const float*)d_in[5];
    const float* g1a  = (const float*)d_in[6];
    const float* b1a  = (const float*)d_in[7];
    const float* w1b  = (const float*)d_in[8];
    const float* g1b  = (const float*)d_in[9];
    const float* b1b  = (const float*)d_in[10];
    const float* w2a  = (const float*)d_in[11];
    const float* g2a  = (const float*)d_in[12];
    const float* b2a  = (const float*)d_in[13];
    const float* w2b  = (const float*)d_in[14];
    const float* g2b  = (const float*)d_in[15];
    const float* b2b  = (const float*)d_in[16];
    const float* w3a  = (const float*)d_in[17];
    const float* g3a  = (const float*)d_in[18];
    const float* b3a  = (const float*)d_in[19];
    const float* w3b  = (const float*)d_in[20];
    const float* g3b  = (const float*)d_in[21];
    const float* b3b  = (const float*)d_in[22];
    const float* wc1  = (const float*)d_in[23];
    const float* gc1  = (const float*)d_in[24];
    const float* bc1  = (const float*)d_in[25];
    const float* wc2  = (const float*)d_in[26];
    const float* gc2  = (const float*)d_in[27];
    const float* bc2  = (const float*)d_in[28];
    const float* wc3  = (const float*)d_in[29];
    const float* bc3  = (const float*)d_in[30];

    k_zero<<<40, 256>>>();
    k_lin_in<<<NB_/16, 64>>>(x, w_in);
    k_coef<<<1, 64>>>(0, (float)NB_, gin, bin);
    k_bnact0<<<(NB_*64 + 255)/256, 256>>>();

    // edge conv 1: in 64 ch -> 64
    k_knn<64><<<B_, 64>>>(0);
    k_gemm_uy<64,64><<<NB_/8, 64>>>(0, w1a);
    k_stats_a<64><<<B_, 64>>>(1);
    k_coef<<<1, 64>>>(1, (float)NE_, g1a, b1a);
    k_gemm_b<64,64><<<NB_, 32>>>(w1b, 1, 2);
    k_coef<<<1, 64>>>(2, (float)NE_, g1b, b1b);
    k_scatter<64><<<B_, 64>>>(2, 1);

    // edge conv 2: in 64 ch -> 128
    k_knn<64><<<B_, 64>>>(1);
    k_gemm_uy<64,128><<<NB_/8, 128>>>(1, w2a);
    k_stats_a<128><<<B_, 128>>>(3);
    k_coef<<<1, 128>>>(3, (float)NE_, g2a, b2a);
    k_gemm_b<128,128><<<NB_, 64>>>(w2b, 3, 4);
    k_coef<<<1, 128>>>(4, (float)NE_, g2b, b2b);
    k_scatter<128><<<B_, 128>>>(4, 2);

    // edge conv 3: in 128 ch -> 256
    k_knn<128><<<B_, 64>>>(2);
    k_gemm_uy<128,256><<<NB_/8, 256>>>(2, w3a);
    k_stats_a<256><<<B_, 256>>>(5);
    k_coef<<<1, 256>>>(5, (float)NE_, g3a, b3a);
    k_gemm_b<256,256><<<NB_, 128>>>(w3b, 5, 6);
    k_coef<<<1, 256>>>(6, (float)NE_, g3b, b3b);
    k_scatter<256><<<B_, 256>>>(6, 3);

    // head
    k_pool<<<B_, 448>>>();
    k_fc1<<<B_, 512>>>(wc1);
    k_coef<<<1, 512>>>(7, (float)B_, gc1, bc1);
    k_fc2<<<B_, 256>>>(wc2);
    k_coef<<<1, 256>>>(8, (float)B_, gc2, bc2);
    k_out<<<B_, 256>>>(wc3, bc3, (float*)d_out);
}